// round 9
// baseline (speedup 1.0000x reference)
#include <cuda_runtime.h>
#include <cstdint>

// ---------------------------------------------------------------------------
// Problem constants
// ---------------------------------------------------------------------------
#define DIN   4096
#define DOUT  4096
#define MTOT  8192
#define NCHUNK 96          // 3 passes x 32 chunks (128 int8 k-elems per chunk)
#define BM    128
#define BN    128
#define NSTAGE 3
#define STAGE_BYTES 32768  // A 16KB + B 16KB (128 rows x 128B)
#define SMEM_TOTAL (NSTAGE * STAGE_BYTES)   // 96 KB
static __device__ __constant__ float kScaling = 2.0f;   // 32 / rank(16)

// quantization: x = s1*X1 + s2*X2,  w = t1*W1 + t2*W2,  s2=s1/128, t2=t1/128
#define INV_S1 15.875f        // 127/8
#define S1     (8.0f/127.0f)
#define INV_S2 2032.0f        // 127*128/8
#define INV_T1 1016.0f        // 127/0.125
#define T1     (0.125f/127.0f)
#define INV_T2 130048.0f      // 127*128/0.125
#define OUT_SCALE (1.0f/16129.0f)   // s1*t1

// ---------------------------------------------------------------------------
// Device-global scratch
// ---------------------------------------------------------------------------
__device__ uint8_t g_X1[(size_t)MTOT * DIN];
__device__ uint8_t g_X2[(size_t)MTOT * DIN];
__device__ uint8_t g_W1[(size_t)DOUT * DIN];
__device__ uint8_t g_W2[(size_t)DOUT * DIN];
__device__ int g_flags[2];
__device__ int g_mode;

// ---------------------------------------------------------------------------
// Helpers (baseline PTX only)
// ---------------------------------------------------------------------------
__device__ __forceinline__ uint32_t smem_u32(const void* p) {
    uint32_t a;
    asm("{ .reg .u64 t; cvta.to.shared.u64 t, %1; cvt.u32.u64 %0, t; }" : "=r"(a) : "l"(p));
    return a;
}
__device__ __forceinline__ void cp_async16(uint32_t dst, const void* src) {
    asm volatile("cp.async.cg.shared.global [%0], [%1], 16;"
                 :: "r"(dst), "l"(__cvta_generic_to_global(src)));
}
#define CP_COMMIT() asm volatile("cp.async.commit_group;" ::: "memory")
#define CP_WAIT(n)  asm volatile("cp.async.wait_group %0;" :: "n"(n) : "memory")

__device__ __forceinline__ uint32_t swz(uint32_t o) { return o ^ ((o >> 3) & 0x70); }

__device__ __forceinline__ void ldsm_x4(uint32_t* r, uint32_t addr) {
    asm volatile("ldmatrix.sync.aligned.m8n8.x4.shared.b16 {%0,%1,%2,%3}, [%4];"
                 : "=r"(r[0]), "=r"(r[1]), "=r"(r[2]), "=r"(r[3]) : "r"(addr));
}
// int8 IMMA: m16n8k32, s8 x s8 -> s32. Fragment layout = fp16 k16 layout with
// each b16 element replaced by 2 consecutive int8 along k (validated pattern in R6).
__device__ __forceinline__ void mma_s8(int* c, const uint32_t* a,
                                       uint32_t b0, uint32_t b1) {
    asm volatile(
        "mma.sync.aligned.m16n8k32.row.col.s32.s8.s8.s32 "
        "{%0,%1,%2,%3}, {%4,%5,%6,%7}, {%8,%9}, {%0,%1,%2,%3};"
        : "+r"(c[0]), "+r"(c[1]), "+r"(c[2]), "+r"(c[3])
        : "r"(a[0]), "r"(a[1]), "r"(a[2]), "r"(a[3]), "r"(b0), "r"(b1));
}

__device__ __forceinline__ int q_clamp(float v) {
    int q = __float2int_rn(v);
    return max(-127, min(127, q));
}
// two-level int8 quantize of one float; returns packed (q1,q2) as bytes
__device__ __forceinline__ void quant2(float v, float inv1, float lvl1, float inv2,
                                       uint32_t& b1, uint32_t& b2) {
    int q1 = q_clamp(v * inv1);
    float r = v - (float)q1 * lvl1;
    int q2 = __float2int_rn(r * inv2);    // |q2| <= 65, no clamp needed
    b1 = (uint32_t)(uint8_t)(int8_t)q1;
    b2 = (uint32_t)(uint8_t)(int8_t)q2;
}

// ---------------------------------------------------------------------------
// Mask dtype detection (first 16MB scan = safe lower bound for all dtypes)
// ---------------------------------------------------------------------------
__global__ void reset_flags_kernel() { g_flags[0] = 0; g_flags[1] = 0; }

__global__ void detect_mask_kernel(const unsigned int* __restrict__ w, int nwords) {
    int notF = 0, notI = 0;
    int stride = gridDim.x * blockDim.x;
    for (int i = blockIdx.x * blockDim.x + threadIdx.x; i < nwords; i += stride) {
        unsigned int v = w[i];
        if (v != 0u && v != 0x3F800000u) notF = 1;
        if (v > 1u)                       notI = 1;
    }
    notF = __any_sync(0xFFFFFFFFu, notF);
    notI = __any_sync(0xFFFFFFFFu, notI);
    if ((threadIdx.x & 31) == 0) {
        if (notF) atomicOr(&g_flags[0], 1);
        if (notI) atomicOr(&g_flags[1], 1);
    }
}
__global__ void resolve_mode_kernel() {
    g_mode = (g_flags[0] == 0) ? 0 : ((g_flags[1] == 0) ? 1 : 2);
}

// ---------------------------------------------------------------------------
// Fused prologue:
//   blocks [0, 4096)    : fold W row -> two-level int8 (W1, W2)
//   blocks [4096, 8192) : convert 2 rows of X -> two-level int8 (X1, X2)
// ---------------------------------------------------------------------------
__global__ void prep_kernel(const float* __restrict__ W,
                            const float* __restrict__ lora_A,
                            const float* __restrict__ lora_B,
                            const float* __restrict__ delta,
                            const void*  __restrict__ maskp,
                            const float* __restrict__ x) {
    if (blockIdx.x < DOUT) {
        // ---------------- fold one W row ----------------
        const int o = blockIdx.x;
        __shared__ float br[16];
        if (threadIdx.x < 16) br[threadIdx.x] = lora_B[o * 16 + threadIdx.x] * kScaling;
        __syncthreads();

        const int mode = g_mode;
        const size_t rowoff = (size_t)o * DIN;

        for (int d = threadIdx.x * 4; d < DIN; d += blockDim.x * 4) {
            float4 w4 = *(const float4*)(W + rowoff + d);
            float4 dl = *(const float4*)(delta + rowoff + d);

            float m0, m1, m2, m3;
            if (mode == 0) {
                float4 mf = *(const float4*)((const float*)maskp + rowoff + d);
                m0 = mf.x; m1 = mf.y; m2 = mf.z; m3 = mf.w;
            } else if (mode == 1) {
                int4 mi = *(const int4*)((const int*)maskp + rowoff + d);
                m0 = mi.x ? 1.f : 0.f; m1 = mi.y ? 1.f : 0.f;
                m2 = mi.z ? 1.f : 0.f; m3 = mi.w ? 1.f : 0.f;
            } else {
                uchar4 mu = *(const uchar4*)((const unsigned char*)maskp + rowoff + d);
                m0 = mu.x ? 1.f : 0.f; m1 = mu.y ? 1.f : 0.f;
                m2 = mu.z ? 1.f : 0.f; m3 = mu.w ? 1.f : 0.f;
            }

            float l0 = 0.f, l1 = 0.f, l2 = 0.f, l3 = 0.f;
#pragma unroll
            for (int r = 0; r < 16; r++) {
                float4 a4 = *(const float4*)(lora_A + (size_t)r * DIN + d);
                float s = br[r];
                l0 = fmaf(s, a4.x, l0); l1 = fmaf(s, a4.y, l1);
                l2 = fmaf(s, a4.z, l2); l3 = fmaf(s, a4.w, l3);
            }

            float v[4];
            v[0] = w4.x + dl.x * m0 + l0;
            v[1] = w4.y + dl.y * m1 + l1;
            v[2] = w4.z + dl.z * m2 + l2;
            v[3] = w4.w + dl.w * m3 + l3;

            uint32_t p1 = 0, p2 = 0;
#pragma unroll
            for (int q = 0; q < 4; q++) {
                uint32_t b1, b2;
                quant2(v[q], INV_T1, T1, INV_T2, b1, b2);
                p1 |= b1 << (q * 8);
                p2 |= b2 << (q * 8);
            }
            *(uint32_t*)(g_W1 + rowoff + d) = p1;
            *(uint32_t*)(g_W2 + rowoff + d) = p2;
        }
    } else {
        // ---------------- convert 2 rows of X ----------------
        const size_t rowbase = (size_t)(blockIdx.x - DOUT) * 2 * DIN;
#pragma unroll
        for (int it = 0; it < 8; it++) {
            size_t base = rowbase + ((size_t)it * blockDim.x + threadIdx.x) * 4;
            float4 a = *(const float4*)(x + base);
            float v[4] = {a.x, a.y, a.z, a.w};
            uint32_t p1 = 0, p2 = 0;
#pragma unroll
            for (int q = 0; q < 4; q++) {
                uint32_t b1, b2;
                quant2(v[q], INV_S1, S1, INV_S2, b1, b2);
                p1 |= b1 << (q * 8);
                p2 |= b2 << (q * 8);
            }
            *(uint32_t*)(g_X1 + base) = p1;
            *(uint32_t*)(g_X2 + base) = p2;
        }
    }
}

// ---------------------------------------------------------------------------
// int8 IMMA GEMM, 3 passes sharing one s32 accumulator:
//   chunks  0..31 : X1·W2   (scale s1*t2 = s1*t1/128)
//   chunks 32..63 : X2·W1   (scale s2*t1 = s1*t1/128)
//   --- acc = (acc+64) >> 7 ---
//   chunks 64..95 : X1·W1   (scale s1*t1)
// out = s1*t1 * acc + bias
// 8 warps (4m x 2n), warp tile 32x64, 3-stage cp.async pipe, 2 CTA/SM.
// ---------------------------------------------------------------------------
__global__ __launch_bounds__(256, 2)
void gemm_kernel(const float* __restrict__ bias, float* __restrict__ out) {
    extern __shared__ __align__(1024) char smem[];
    const uint32_t sbase = smem_u32(smem);
    const int tid = threadIdx.x;
    const int lane = tid & 31;
    const int wid = tid >> 5;
    const int warpM = wid >> 1;           // 0..3
    const int warpN = wid & 1;            // 0..1
    const int bm = blockIdx.x * BM;       // m fastest → W stays L2-resident
    const int bn = blockIdx.y * BN;

    // loader mapping: 4 A-slots + 4 B-slots of 16B per thread per chunk
    int rowL[4];  uint32_t dstL[4];  int colByte[4];
#pragma unroll
    for (int i = 0; i < 4; i++) {
        int slot = tid + 256 * i;         // 0..1023
        rowL[i] = slot >> 3;              // 0..127
        colByte[i] = (slot & 7) * 16;
        dstL[i] = swz((uint32_t)(rowL[i] * 128 + colByte[i]));
    }

    // ldmatrix per-lane swizzled offsets (full-offset swizzle)
    const int arow  = (lane & 7) + ((lane >> 3) & 1) * 8;
    const int acol  = ((lane >> 4) & 1) * 16;           // byte
    const int brow  = (lane & 7) + ((lane >> 4) & 1) * 8;
    const int bcol  = ((lane >> 3) & 1) * 16;           // byte
    uint32_t relA[2][4], relB[4][4];
#pragma unroll
    for (int mt = 0; mt < 2; mt++)
#pragma unroll
        for (int ks = 0; ks < 4; ks++)
            relA[mt][ks] = swz((uint32_t)((warpM * 32 + mt * 16 + arow) * 128 + ks * 32 + acol));
#pragma unroll
    for (int p = 0; p < 4; p++)
#pragma unroll
        for (int ks = 0; ks < 4; ks++)
            relB[p][ks] = swz((uint32_t)((warpN * 64 + p * 16 + brow) * 128 + ks * 32 + bcol));

    int acc[2][8][4];
#pragma unroll
    for (int mt = 0; mt < 2; mt++)
#pragma unroll
        for (int nt = 0; nt < 8; nt++)
#pragma unroll
            for (int q = 0; q < 4; q++) acc[mt][nt][q] = 0;

    auto load_chunk = [&](int c, int stage) {
        const int pass = c >> 5;
        const size_t kb = (size_t)(c & 31) * 128;
        const uint8_t* Ab = (pass == 1) ? g_X2 : g_X1;
        const uint8_t* Bb = (pass == 0) ? g_W2 : g_W1;
        const uint32_t aB = sbase + stage * STAGE_BYTES;
        const uint32_t bB = aB + 16384;
#pragma unroll
        for (int i = 0; i < 4; i++)
            cp_async16(aB + dstL[i], Ab + (size_t)(bm + rowL[i]) * DIN + kb + colByte[i]);
#pragma unroll
        for (int i = 0; i < 4; i++)
            cp_async16(bB + dstL[i], Bb + (size_t)(bn + rowL[i]) * DIN + kb + colByte[i]);
    };

    // prologue: 2 chunks in flight
    load_chunk(0, 0); CP_COMMIT();
    load_chunk(1, 1); CP_COMMIT();

    for (int c = 0; c < NCHUNK; c++) {
        if (c + 1 < NCHUNK) { CP_WAIT(1); } else { CP_WAIT(0); }
        __syncthreads();
        if (c + 2 < NCHUNK) { load_chunk(c + 2, (c + 2) % NSTAGE); CP_COMMIT(); }

        const uint32_t aB = sbase + (c % NSTAGE) * STAGE_BYTES;
        const uint32_t bB = aB + 16384;
#pragma unroll
        for (int ks = 0; ks < 4; ks++) {
            uint32_t a[2][4];
            ldsm_x4(a[0], aB + relA[0][ks]);
            ldsm_x4(a[1], aB + relA[1][ks]);
            uint32_t b[4][4];
#pragma unroll
            for (int p = 0; p < 4; p++) ldsm_x4(b[p], bB + relB[p][ks]);
#pragma unroll
            for (int mt = 0; mt < 2; mt++)
#pragma unroll
                for (int nt = 0; nt < 8; nt++)
                    mma_s8(acc[mt][nt], a[mt],
                           b[nt >> 1][(nt & 1) * 2], b[nt >> 1][(nt & 1) * 2 + 1]);
        }

        // pass boundary: correction passes done -> rescale into s1*t1 units
        if (c == 63) {
#pragma unroll
            for (int mt = 0; mt < 2; mt++)
#pragma unroll
                for (int nt = 0; nt < 8; nt++)
#pragma unroll
                    for (int q = 0; q < 4; q++)
                        acc[mt][nt][q] = (acc[mt][nt][q] + 64) >> 7;
        }
    }

    // epilogue: scale, add bias, float2 stores
    const int group = lane >> 2;
    const int tig   = lane & 3;
#pragma unroll
    for (int nt = 0; nt < 8; nt++) {
        const int col = bn + warpN * 64 + nt * 8 + tig * 2;
        const float2 bv = *(const float2*)(bias + col);
#pragma unroll
        for (int mt = 0; mt < 2; mt++) {
            const int row0 = bm + warpM * 32 + mt * 16 + group;
            float* p0 = out + (size_t)row0 * DOUT + col;
            float* p1 = out + (size_t)(row0 + 8) * DOUT + col;
            *(float2*)p0 = make_float2(
                (float)acc[mt][nt][0] * OUT_SCALE + bv.x,
                (float)acc[mt][nt][1] * OUT_SCALE + bv.y);
            *(float2*)p1 = make_float2(
                (float)acc[mt][nt][2] * OUT_SCALE + bv.x,
                (float)acc[mt][nt][3] * OUT_SCALE + bv.y);
        }
    }
}

// ---------------------------------------------------------------------------
// Launch
// ---------------------------------------------------------------------------
extern "C" void kernel_launch(void* const* d_in, const int* in_sizes, int n_in,
                              void* d_out, int out_size) {
    const float* x      = (const float*)d_in[0];
    const float* W      = (const float*)d_in[1];
    const float* b      = (const float*)d_in[2];
    const float* lora_A = (const float*)d_in[3];
    const float* lora_B = (const float*)d_in[4];
    const float* delta  = (const float*)d_in[5];
    const void*  mask   = d_in[6];

    static bool attr_done = false;
    if (!attr_done) {
        cudaFuncSetAttribute(gemm_kernel,
                             cudaFuncAttributeMaxDynamicSharedMemorySize, SMEM_TOTAL);
        attr_done = true;
    }

    reset_flags_kernel<<<1, 1>>>();
    detect_mask_kernel<<<256, 256>>>((const unsigned int*)mask, 4 * 1024 * 1024);
    resolve_mode_kernel<<<1, 1>>>();

    // fused fold (4096 blocks) + X convert (4096 blocks)
    prep_kernel<<<DOUT + MTOT / 2, 256>>>(W, lora_A, lora_B, delta, mask, x);

    dim3 grid(MTOT / BM, DOUT / BN);   // (64, 32), m fastest
    gemm_kernel<<<grid, 256, SMEM_TOTAL>>>(b, (float*)d_out);
}

// round 10
// speedup vs baseline: 7.8974x; 7.8974x over previous
#include <cuda_runtime.h>
#include <cuda_fp16.h>
#include <cstdint>

// ---------------------------------------------------------------------------
// Problem constants
// ---------------------------------------------------------------------------
#define DIN   4096
#define DOUT  4096
#define MTOT  8192
#define BK    64                          // fp16 k-elems per chunk (128 B/row)
#define NCHUNK (DIN / BK)                 // 64 — single fp16 pass
#define BM    128
#define BN    128
#define NSTAGE 3
#define STAGE_BYTES 32768                 // A 16KB + B 16KB
#define SMEM_TOTAL (NSTAGE * STAGE_BYTES) // 96 KB
static __device__ __constant__ float kScaling = 2.0f;   // 32 / rank(16)

// ---------------------------------------------------------------------------
// Device-global scratch
// ---------------------------------------------------------------------------
__device__ __half g_Xh[(size_t)MTOT * DIN];   // fp16(x)
__device__ __half g_Wh[(size_t)DOUT * DIN];   // fp16(W_eff)
__device__ int g_flags[2];

// ---------------------------------------------------------------------------
// Helpers (baseline PTX only — compiles at compute_103)
// ---------------------------------------------------------------------------
__device__ __forceinline__ uint32_t smem_u32(const void* p) {
    uint32_t a;
    asm("{ .reg .u64 t; cvta.to.shared.u64 t, %1; cvt.u32.u64 %0, t; }" : "=r"(a) : "l"(p));
    return a;
}
__device__ __forceinline__ void cp_async16(uint32_t dst, const void* src) {
    asm volatile("cp.async.cg.shared.global [%0], [%1], 16;"
                 :: "r"(dst), "l"(__cvta_generic_to_global(src)));
}
#define CP_COMMIT() asm volatile("cp.async.commit_group;" ::: "memory")
#define CP_WAIT(n)  asm volatile("cp.async.wait_group %0;" :: "n"(n) : "memory")

__device__ __forceinline__ uint32_t swz(uint32_t o) { return o ^ ((o >> 3) & 0x70); }

__device__ __forceinline__ void ldsm_x4(uint32_t* r, uint32_t addr) {
    asm volatile("ldmatrix.sync.aligned.m8n8.x4.shared.b16 {%0,%1,%2,%3}, [%4];"
                 : "=r"(r[0]), "=r"(r[1]), "=r"(r[2]), "=r"(r[3]) : "r"(addr));
}
__device__ __forceinline__ void mma_fp16(float* c, const uint32_t* a,
                                         uint32_t b0, uint32_t b1) {
    asm volatile(
        "mma.sync.aligned.m16n8k16.row.col.f32.f16.f16.f32 "
        "{%0,%1,%2,%3}, {%4,%5,%6,%7}, {%8,%9}, {%0,%1,%2,%3};"
        : "+f"(c[0]), "+f"(c[1]), "+f"(c[2]), "+f"(c[3])
        : "r"(a[0]), "r"(a[1]), "r"(a[2]), "r"(a[3]), "r"(b0), "r"(b1));
}

// ---------------------------------------------------------------------------
// Mask dtype detection (first 16MB scan = safe lower bound for all dtypes)
// ---------------------------------------------------------------------------
__global__ void reset_flags_kernel() { g_flags[0] = 0; g_flags[1] = 0; }

__global__ void detect_mask_kernel(const unsigned int* __restrict__ w, int nwords) {
    int notF = 0, notI = 0;
    int stride = gridDim.x * blockDim.x;
    for (int i = blockIdx.x * blockDim.x + threadIdx.x; i < nwords; i += stride) {
        unsigned int v = w[i];
        if (v != 0u && v != 0x3F800000u) notF = 1;
        if (v > 1u)                       notI = 1;
    }
    notF = __any_sync(0xFFFFFFFFu, notF);
    notI = __any_sync(0xFFFFFFFFu, notI);
    if ((threadIdx.x & 31) == 0) {
        if (notF) atomicOr(&g_flags[0], 1);
        if (notI) atomicOr(&g_flags[1], 1);
    }
}

// ---------------------------------------------------------------------------
// Fused prologue (mode resolved inline from g_flags — no resolve kernel):
//   blocks [0, 4096)     : fold row o — W_eff = W + delta*mask + 2*(B@A) → fp16
//   blocks [4096, 8192)  : convert 2 rows of X → fp16
// Streaming convert blocks overlap the FFMA-latency-limited fold blocks.
// ---------------------------------------------------------------------------
__global__ void prep_kernel(const float* __restrict__ W,
                            const float* __restrict__ lora_A,
                            const float* __restrict__ lora_B,
                            const float* __restrict__ delta,
                            const void*  __restrict__ maskp,
                            const float* __restrict__ x) {
    if (blockIdx.x < DOUT) {
        // ---------------- fold one W row ----------------
        const int o = blockIdx.x;
        __shared__ float br[16];
        if (threadIdx.x < 16) br[threadIdx.x] = lora_B[o * 16 + threadIdx.x] * kScaling;
        __syncthreads();

        // mode: 0 = f32 {0,1.0f}, 1 = int32 {0,1}, 2 = uint8 {0,1}
        const int mode = (g_flags[0] == 0) ? 0 : ((g_flags[1] == 0) ? 1 : 2);
        const size_t rowoff = (size_t)o * DIN;

        for (int d = threadIdx.x * 4; d < DIN; d += blockDim.x * 4) {
            float4 w4 = *(const float4*)(W + rowoff + d);
            float4 dl = *(const float4*)(delta + rowoff + d);

            float m0, m1, m2, m3;
            if (mode == 0) {
                float4 mf = *(const float4*)((const float*)maskp + rowoff + d);
                m0 = mf.x; m1 = mf.y; m2 = mf.z; m3 = mf.w;
            } else if (mode == 1) {
                int4 mi = *(const int4*)((const int*)maskp + rowoff + d);
                m0 = mi.x ? 1.f : 0.f; m1 = mi.y ? 1.f : 0.f;
                m2 = mi.z ? 1.f : 0.f; m3 = mi.w ? 1.f : 0.f;
            } else {
                uchar4 mu = *(const uchar4*)((const unsigned char*)maskp + rowoff + d);
                m0 = mu.x ? 1.f : 0.f; m1 = mu.y ? 1.f : 0.f;
                m2 = mu.z ? 1.f : 0.f; m3 = mu.w ? 1.f : 0.f;
            }

            float l0 = 0.f, l1 = 0.f, l2 = 0.f, l3 = 0.f;
#pragma unroll
            for (int r = 0; r < 16; r++) {
                float4 a4 = *(const float4*)(lora_A + (size_t)r * DIN + d);
                float s = br[r];
                l0 = fmaf(s, a4.x, l0); l1 = fmaf(s, a4.y, l1);
                l2 = fmaf(s, a4.z, l2); l3 = fmaf(s, a4.w, l3);
            }

            float v0 = w4.x + dl.x * m0 + l0;
            float v1 = w4.y + dl.y * m1 + l1;
            float v2 = w4.z + dl.z * m2 + l2;
            float v3 = w4.w + dl.w * m3 + l3;

            __half2 h01 = __floats2half2_rn(v0, v1);
            __half2 h23 = __floats2half2_rn(v2, v3);
            uint2 H;
            H.x = *(const uint32_t*)&h01;
            H.y = *(const uint32_t*)&h23;
            *(uint2*)((char*)g_Wh + (rowoff + d) * 2) = H;
        }
    } else {
        // ---------------- convert 2 rows of X ----------------
        const size_t rowbase = (size_t)(blockIdx.x - DOUT) * 2 * DIN;
#pragma unroll
        for (int it = 0; it < 4; it++) {
            size_t base = rowbase + ((size_t)it * blockDim.x + threadIdx.x) * 8;
            float4 a = *(const float4*)(x + base);
            float4 b = *(const float4*)(x + base + 4);
            __half2 h0 = __floats2half2_rn(a.x, a.y);
            __half2 h1 = __floats2half2_rn(a.z, a.w);
            __half2 h2 = __floats2half2_rn(b.x, b.y);
            __half2 h3 = __floats2half2_rn(b.z, b.w);
            uint4 H;
            H.x = *(const uint32_t*)&h0; H.y = *(const uint32_t*)&h1;
            H.z = *(const uint32_t*)&h2; H.w = *(const uint32_t*)&h3;
            *(uint4*)((char*)g_Xh + base * 2) = H;
        }
    }
}

// ---------------------------------------------------------------------------
// fp16 HMMA GEMM: out[128x128 tile] = Xh[128,4096]·Wh[128,4096]^T + bias
// 8 warps (4m × 2n), warp tile 32x64, mma m16n8k16, 3-stage cp.async pipe.
// ---------------------------------------------------------------------------
__global__ __launch_bounds__(256, 2)
void gemm_kernel(const float* __restrict__ bias, float* __restrict__ out) {
    extern __shared__ __align__(1024) char smem[];
    const uint32_t sbase = smem_u32(smem);
    const int tid = threadIdx.x;
    const int lane = tid & 31;
    const int wid = tid >> 5;
    const int warpM = wid >> 1;           // 0..3
    const int warpN = wid & 1;            // 0..1
    const int bm = blockIdx.x * BM;       // m fastest → W stays L2-resident
    const int bn = blockIdx.y * BN;

    // loader mapping: 4 A-slots + 4 B-slots of 16B per thread per chunk
    int rowL[4];  uint32_t dstL[4];  int colL[4];
#pragma unroll
    for (int i = 0; i < 4; i++) {
        int slot = tid + 256 * i;         // 0..1023
        rowL[i] = slot >> 3;              // 0..127
        colL[i] = (slot & 7) * 8;         // fp16 col
        dstL[i] = swz((uint32_t)(rowL[i] * 128 + (slot & 7) * 16));
    }

    // ldmatrix per-lane swizzled offsets (full-offset swizzle — R4 lesson)
    const int arow  = (lane & 7) + ((lane >> 3) & 1) * 8;
    const int acol  = ((lane >> 4) & 1) * 16;           // byte
    const int brow  = (lane & 7) + ((lane >> 4) & 1) * 8;
    const int bcol  = ((lane >> 3) & 1) * 16;           // byte
    uint32_t relA[2][4], relB[4][4];
#pragma unroll
    for (int mt = 0; mt < 2; mt++)
#pragma unroll
        for (int ks = 0; ks < 4; ks++)
            relA[mt][ks] = swz((uint32_t)((warpM * 32 + mt * 16 + arow) * 128 + ks * 32 + acol));
#pragma unroll
    for (int p = 0; p < 4; p++)
#pragma unroll
        for (int ks = 0; ks < 4; ks++)
            relB[p][ks] = swz((uint32_t)((warpN * 64 + p * 16 + brow) * 128 + ks * 32 + bcol));

    float acc[2][8][4];
#pragma unroll
    for (int mt = 0; mt < 2; mt++)
#pragma unroll
        for (int nt = 0; nt < 8; nt++)
#pragma unroll
            for (int q = 0; q < 4; q++) acc[mt][nt][q] = 0.f;

    auto load_chunk = [&](int c, int stage) {
        const int kk = c << 6;
        const uint32_t aB = sbase + stage * STAGE_BYTES;
        const uint32_t bB = aB + 16384;
#pragma unroll
        for (int i = 0; i < 4; i++)
            cp_async16(aB + dstL[i], g_Xh + (size_t)(bm + rowL[i]) * DIN + kk + colL[i]);
#pragma unroll
        for (int i = 0; i < 4; i++)
            cp_async16(bB + dstL[i], g_Wh + (size_t)(bn + rowL[i]) * DIN + kk + colL[i]);
    };

    // prologue: 2 chunks in flight
    load_chunk(0, 0); CP_COMMIT();
    load_chunk(1, 1); CP_COMMIT();

    int curStage = 0;      // stage of chunk c
    int nextStage = 2;     // stage for chunk c+2
    for (int c = 0; c < NCHUNK; c++) {
        if (c + 1 < NCHUNK) { CP_WAIT(1); } else { CP_WAIT(0); }
        __syncthreads();
        if (c + 2 < NCHUNK) {
            load_chunk(c + 2, nextStage);
            CP_COMMIT();
        }

        const uint32_t aB = sbase + curStage * STAGE_BYTES;
        const uint32_t bB = aB + 16384;
#pragma unroll
        for (int ks = 0; ks < 4; ks++) {
            uint32_t a[2][4];
            ldsm_x4(a[0], aB + relA[0][ks]);
            ldsm_x4(a[1], aB + relA[1][ks]);
            uint32_t b[4][4];
#pragma unroll
            for (int p = 0; p < 4; p++) ldsm_x4(b[p], bB + relB[p][ks]);
#pragma unroll
            for (int mt = 0; mt < 2; mt++)
#pragma unroll
                for (int nt = 0; nt < 8; nt++)
                    mma_fp16(acc[mt][nt], a[mt],
                             b[nt >> 1][(nt & 1) * 2], b[nt >> 1][(nt & 1) * 2 + 1]);
        }

        curStage  = (curStage  == NSTAGE - 1) ? 0 : curStage + 1;
        nextStage = (nextStage == NSTAGE - 1) ? 0 : nextStage + 1;
    }

    // epilogue: add bias, float2 stores
    const int group = lane >> 2;
    const int tig   = lane & 3;
#pragma unroll
    for (int nt = 0; nt < 8; nt++) {
        const int col = bn + warpN * 64 + nt * 8 + tig * 2;
        const float2 bv = *(const float2*)(bias + col);
#pragma unroll
        for (int mt = 0; mt < 2; mt++) {
            const int row0 = bm + warpM * 32 + mt * 16 + group;
            float* p0 = out + (size_t)row0 * DOUT + col;
            float* p1 = out + (size_t)(row0 + 8) * DOUT + col;
            *(float2*)p0 = make_float2(acc[mt][nt][0] + bv.x, acc[mt][nt][1] + bv.y);
            *(float2*)p1 = make_float2(acc[mt][nt][2] + bv.x, acc[mt][nt][3] + bv.y);
        }
    }
}

// ---------------------------------------------------------------------------
// Launch: reset → detect → fused prep → GEMM (3 small + 2 big launches)
// ---------------------------------------------------------------------------
extern "C" void kernel_launch(void* const* d_in, const int* in_sizes, int n_in,
                              void* d_out, int out_size) {
    const float* x      = (const float*)d_in[0];
    const float* W      = (const float*)d_in[1];
    const float* b      = (const float*)d_in[2];
    const float* lora_A = (const float*)d_in[3];
    const float* lora_B = (const float*)d_in[4];
    const float* delta  = (const float*)d_in[5];
    const void*  mask   = d_in[6];

    static bool attr_done = false;
    if (!attr_done) {
        cudaFuncSetAttribute(gemm_kernel,
                             cudaFuncAttributeMaxDynamicSharedMemorySize, SMEM_TOTAL);
        attr_done = true;
    }

    reset_flags_kernel<<<1, 1>>>();
    detect_mask_kernel<<<512, 256>>>((const unsigned int*)mask, 4 * 1024 * 1024);

    // fused fold (4096 blocks) + X convert (4096 blocks); mode from g_flags
    prep_kernel<<<DOUT + MTOT / 2, 256>>>(W, lora_A, lora_B, delta, mask, x);

    dim3 grid(MTOT / BM, DOUT / BN);   // (64, 32), m fastest
    gemm_kernel<<<grid, 256, SMEM_TOTAL>>>(b, (float*)d_out);
}